// round 15
// baseline (speedup 1.0000x reference)
#include <cuda_runtime.h>
#include <cstdint>

#define LL    256   // sequence length
#define EE    64    // embed dim
#define GG    256   // 4H
#define NSEQ  2048  // B*S
#define VV    6000  // vocab
#define VCAP  6016  // padded vocab rows in table

typedef unsigned long long u64;

// 12.3 MB scratch: T[dir][v][j*4+g] = embed[v] @ Wk_dir + b_dir  (L2-resident)
__device__ float g_tab[(size_t)2 * VCAP * GG];

__device__ __forceinline__ void fma2(u64 &d, u64 a, u64 b) {
    asm("fma.rn.f32x2 %0, %1, %2, %0;" : "+l"(d) : "l"(a), "l"(b));
}
__device__ __forceinline__ u64 pack2(float lo, float hi) {
    u64 r; asm("mov.b64 %0, {%1, %2};" : "=l"(r) : "f"(lo), "f"(hi)); return r;
}
__device__ __forceinline__ float hsum2(u64 v) {
    float lo, hi; asm("mov.b64 {%0, %1}, %2;" : "=f"(lo), "=f"(hi) : "l"(v));
    return lo + hi;
}
__device__ __forceinline__ float tanha(float x) {
    float y; asm("tanh.approx.f32 %0, %1;" : "=f"(y) : "f"(x)); return y;
}

#define XSTRIDE 68

// fp32 weight SMEM layout (K-paired for f32x2), two arrays:
//   w0[e2*256 + j*4 + g*2 + s] = W[(2*e2+s)*GG + g*64 + j]      g in {i,f}
//   w1[e2*256 + j*4 + g*2 + s] = W[(2*e2+s)*GG + (g+2)*64 + j]  g in {g,o}
template<int NT>
__device__ __forceinline__ void load_weights(float* w0, float* w1,
                                             const float* W, int tid) {
    for (int idx = tid; idx < 8192; idx += NT) {
        int e2  = idx >> 8;
        int rem = idx & 255;
        int jj  = rem >> 2;
        int g   = (rem >> 1) & 1;
        int s   = rem & 1;
        int e   = 2 * e2 + s;
        w0[idx] = W[e * GG + g * 64 + jj];
        w1[idx] = W[e * GG + (g + 2) * 64 + jj];
    }
}

// ============================================================================
// Kernel 1 (unchanged R14): vocab table T[dir][v] = embed[v] @ Wk_dir + b_dir
// ============================================================================
#define K1_NTHR 256
#define K1_TILES 8
#define K1_ROWS_CTA 128
#define K1_XS_G (2 * 4 * XSTRIDE)
#define K1_SMEM_FLOATS (16384 + 4 * K1_XS_G)

__global__ void __launch_bounds__(K1_NTHR, 1)
tab_kernel(const float* __restrict__ embed,
           const float* __restrict__ Wk_f, const float* __restrict__ b_f,
           const float* __restrict__ Wk_b, const float* __restrict__ b_b)
{
    extern __shared__ float smem[];
    float* wk0 = smem;
    float* wk1 = smem + 8192;

    const int tid = threadIdx.x;
    const int dir = blockIdx.y;
    const float* Wk = dir ? Wk_b : Wk_f;
    const float* bb = dir ? b_b  : b_f;

    load_weights<K1_NTHR>(wk0, wk1, Wk, tid);

    const int j     = tid & 63;
    const int q     = tid >> 6;
    const int barid = q + 1;
    float* xsg = smem + 16384 + q * K1_XS_G;

    const int grow = j >> 4;
    const int ge   = (j & 15) * 4;

    const float bi = bb[j], bf = bb[64 + j], bg = bb[128 + j], bo = bb[192 + j];

    const int v_base = blockIdx.x * K1_ROWS_CTA + q * (K1_TILES * 4);
    float* tb = g_tab + (size_t)dir * VCAP * GG;

    __syncthreads();

    float4 xv;
    {
        int v = v_base + grow; if (v >= VV) v = VV - 1;
        xv = *(const float4*)(embed + (size_t)v * EE + ge);
    }

    int buf = 0;
    for (int tile = 0; tile < K1_TILES; ++tile) {
        float* xs = xsg + buf * (4 * XSTRIDE);
        *(float4*)&xs[grow * XSTRIDE + ge] = xv;
        asm volatile("bar.sync %0, %1;" :: "r"(barid), "r"(64) : "memory");

        if (tile + 1 < K1_TILES) {
            int v = v_base + (tile + 1) * 4 + grow; if (v >= VV) v = VV - 1;
            xv = *(const float4*)(embed + (size_t)v * EE + ge);
        }

        u64 a0[4], a1[4], a2[4], a3[4];
#pragma unroll
        for (int p = 0; p < 4; ++p) {
            a0[p] = pack2(bi, 0.f);
            a1[p] = pack2(bf, 0.f);
            a2[p] = pack2(bg, 0.f);
            a3[p] = pack2(bo, 0.f);
        }

#pragma unroll 2
        for (int e4 = 0; e4 < 16; ++e4) {
            const ulonglong2 wA0 = *(const ulonglong2*)(wk0 + (2 * e4) * 256 + j * 4);
            const ulonglong2 wB0 = *(const ulonglong2*)(wk1 + (2 * e4) * 256 + j * 4);
            const ulonglong2 wA1 = *(const ulonglong2*)(wk0 + (2 * e4 + 1) * 256 + j * 4);
            const ulonglong2 wB1 = *(const ulonglong2*)(wk1 + (2 * e4 + 1) * 256 + j * 4);
#pragma unroll
            for (int p = 0; p < 4; ++p) {
                ulonglong2 x4 = *(const ulonglong2*)(xs + p * XSTRIDE + e4 * 4);
                fma2(a0[p], x4.x, wA0.x);
                fma2(a1[p], x4.x, wA0.y);
                fma2(a2[p], x4.x, wB0.x);
                fma2(a3[p], x4.x, wB0.y);
                fma2(a0[p], x4.y, wA1.x);
                fma2(a1[p], x4.y, wA1.y);
                fma2(a2[p], x4.y, wB1.x);
                fma2(a3[p], x4.y, wB1.y);
            }
        }

#pragma unroll
        for (int p = 0; p < 4; ++p) {
            int v = v_base + tile * 4 + p;
            if (v < VV) {
                float4 r;
                r.x = hsum2(a0[p]);
                r.y = hsum2(a1[p]);
                r.z = hsum2(a2[p]);
                r.w = hsum2(a3[p]);
                *(float4*)&tb[(size_t)v * GG + j * 4] = r;
            }
        }
        buf ^= 1;
    }
}

// ============================================================================
// Kernel 2: recurrence, K-split across group pairs. 512 threads = 8 groups
// = 4 pairs x 128 threads. Pair owns 7 rows; side A computes partial z over
// K[0,32), side B over K[32,64). Partials exchanged via SMEM; side A runs
// epilogue for rows 0-3, side B rows 4-6. grid 74 x 2 = 148 CTAs (1/SM).
// ============================================================================
#define NTHR2 512
#define ROWS 28
#define PR   7
#define NCTA_X 74
#define HS_BUF   (ROWS * XSTRIDE)
#define OFF_HS   16384
#define OFF_PART (OFF_HS + 2 * HS_BUF)          // part: 4 pairs x 2 sides x 7 x 64 x 4
#define OFF_IDS  (OFF_PART + 4 * 2 * PR * 256)
#define K2_SMEM_FLOATS (OFF_IDS + ROWS * LL)

__global__ void __launch_bounds__(NTHR2, 1)
rec_kernel(const int* __restrict__ ids,
           const float* __restrict__ Wr_f,
           const float* __restrict__ Wr_b,
           float* __restrict__ out)
{
    extern __shared__ float smem[];
    float* wr0   = smem;
    float* wr1   = smem + 8192;
    float* hsbuf = smem + OFF_HS;
    int*   idss  = (int*)(smem + OFF_IDS);

    const int tid   = threadIdx.x;
    const int dir   = blockIdx.y;
    const int nbase = blockIdx.x * ROWS;
    const float* Wr = dir ? Wr_b : Wr_f;

    load_weights<NTHR2>(wr0, wr1, Wr, tid);

    // stage this CTA's ids (clamped rows for the tail CTA)
    for (int idx = tid; idx < ROWS * LL; idx += NTHR2) {
        int lr = idx / LL;
        int gr = nbase + lr; if (gr >= NSEQ) gr = NSEQ - 1;
        idss[idx] = ids[(size_t)gr * LL + (idx % LL)];
    }

    const int j     = tid & 63;
    const int q     = tid >> 6;       // 0..7
    const int pair  = q >> 1;         // 0..3
    const int side  = q & 1;          // 0: K[0,32)+rows0-3, 1: K[32,64)+rows4-6
    const int barid = pair + 1;
    const int pr0   = pair * PR;
    const int eb    = side * 8;       // e4 base

    float* mypart    = smem + OFF_PART + (pair * 2 + side) * (PR * 256);
    float* theirpart = smem + OFF_PART + (pair * 2 + (side ^ 1)) * (PR * 256);

    const float* tb = g_tab + (size_t)dir * VCAP * GG;

    float c_[4], h_[4];
    float4 pv[4];
    bool rowok[4];
    int  lrow[4];                      // local row (clamped for id lookups)
#pragma unroll
    for (int oi = 0; oi < 4; ++oi) {
        c_[oi] = 0.f; h_[oi] = 0.f;
        int lr = side * 4 + oi;        // local row within pair
        if (lr > PR - 1) lr = PR - 1;  // side1 oi=3 unused
        lrow[oi]  = lr;
        rowok[oi] = (side * 4 + oi <= PR - 1) && (nbase + pr0 + lr < NSEQ);
    }
    const int nown = 4 - side;

    __syncthreads();   // weights + ids ready (only CTA-wide barrier)

    // prefetch table rows for step 0 (owned rows)
    {
        const int te0 = dir ? (LL - 1) : 0;
#pragma unroll
        for (int oi = 0; oi < 4; ++oi) {
            if (oi < nown) {
                int id = idss[(pr0 + lrow[oi]) * LL + te0];
                pv[oi] = *(const float4*)&tb[(size_t)id * GG + j * 4];
            }
        }
    }

    int buf = 0;
    for (int t = 0; t < LL; ++t) {
        const int te = dir ? (LL - 1 - t) : t;
        float* hs  = hsbuf + buf * HS_BUF;
        float* hsn = hsbuf + (buf ^ 1) * HS_BUF;

        // init accumulators: owned rows from table (pre enters once), rest 0
        u64 a0[PR], a1[PR], a2[PR], a3[PR];
#pragma unroll
        for (int p = 0; p < PR; ++p) {
            a0[p] = 0; a1[p] = 0; a2[p] = 0; a3[p] = 0;
        }
        if (side == 0) {
#pragma unroll
            for (int oi = 0; oi < 4; ++oi) {
                a0[oi] = pack2(pv[oi].x, 0.f);
                a1[oi] = pack2(pv[oi].y, 0.f);
                a2[oi] = pack2(pv[oi].z, 0.f);
                a3[oi] = pack2(pv[oi].w, 0.f);
            }
        } else {
#pragma unroll
            for (int oi = 0; oi < 3; ++oi) {
                a0[4 + oi] = pack2(pv[oi].x, 0.f);
                a1[4 + oi] = pack2(pv[oi].y, 0.f);
                a2[4 + oi] = pack2(pv[oi].z, 0.f);
                a3[4 + oi] = pack2(pv[oi].w, 0.f);
            }
        }

        // table gather for step t+1 (L2 hit, lands under compute)
        {
            const int tn = (t + 1 < LL) ? (dir ? (LL - 2 - t) : (t + 1)) : te;
#pragma unroll
            for (int oi = 0; oi < 4; ++oi) {
                if (oi < nown) {
                    int id = idss[(pr0 + lrow[oi]) * LL + tn];
                    pv[oi] = *(const float4*)&tb[(size_t)id * GG + j * 4];
                }
            }
        }

        // matmul: my K-half, all 7 pair rows (h == 0 at t==0: skip)
        if (t != 0) {
#pragma unroll 2
            for (int ee = 0; ee < 8; ++ee) {
                const int e4 = eb + ee;
                const ulonglong2 wA0 = *(const ulonglong2*)(wr0 + (2 * e4) * 256 + j * 4);
                const ulonglong2 wB0 = *(const ulonglong2*)(wr1 + (2 * e4) * 256 + j * 4);
                const ulonglong2 wA1 = *(const ulonglong2*)(wr0 + (2 * e4 + 1) * 256 + j * 4);
                const ulonglong2 wB1 = *(const ulonglong2*)(wr1 + (2 * e4 + 1) * 256 + j * 4);
#pragma unroll
                for (int p = 0; p < PR; ++p) {
                    ulonglong2 h4 = *(const ulonglong2*)(hs + (pr0 + p) * XSTRIDE + e4 * 4);
                    fma2(a0[p], h4.x, wA0.x);
                    fma2(a1[p], h4.x, wA0.y);
                    fma2(a2[p], h4.x, wB0.x);
                    fma2(a3[p], h4.x, wB0.y);
                    fma2(a0[p], h4.y, wA1.x);
                    fma2(a1[p], h4.y, wA1.y);
                    fma2(a2[p], h4.y, wB1.x);
                    fma2(a3[p], h4.y, wB1.y);
                }
            }
        }

        // hsum: keep owned z in regs, store non-owned partials to my slab
        float4 zo[4];
        if (side == 0) {
#pragma unroll
            for (int oi = 0; oi < 4; ++oi) {
                zo[oi].x = hsum2(a0[oi]); zo[oi].y = hsum2(a1[oi]);
                zo[oi].z = hsum2(a2[oi]); zo[oi].w = hsum2(a3[oi]);
            }
#pragma unroll
            for (int p = 4; p < 7; ++p) {
                float4 z;
                z.x = hsum2(a0[p]); z.y = hsum2(a1[p]);
                z.z = hsum2(a2[p]); z.w = hsum2(a3[p]);
                *(float4*)&mypart[p * 256 + j * 4] = z;
            }
        } else {
#pragma unroll
            for (int oi = 0; oi < 3; ++oi) {
                zo[oi].x = hsum2(a0[4 + oi]); zo[oi].y = hsum2(a1[4 + oi]);
                zo[oi].z = hsum2(a2[4 + oi]); zo[oi].w = hsum2(a3[4 + oi]);
            }
#pragma unroll
            for (int p = 0; p < 4; ++p) {
                float4 z;
                z.x = hsum2(a0[p]); z.y = hsum2(a1[p]);
                z.z = hsum2(a2[p]); z.w = hsum2(a3[p]);
                *(float4*)&mypart[p * 256 + j * 4] = z;
            }
        }
        asm volatile("bar.sync %0, %1;" :: "r"(barid), "r"(128) : "memory");

        // epilogue for owned rows: z = zo + partner partial
#pragma unroll
        for (int oi = 0; oi < 4; ++oi) {
            if (oi < nown) {
                const int p = side * 4 + oi;
                float4 zp = *(const float4*)&theirpart[p * 256 + j * 4];
                float zi = zo[oi].x + zp.x;
                float zf = zo[oi].y + zp.y;
                float zg = zo[oi].z + zp.z;
                float zz = zo[oi].w + zp.w;
                float ig  = fmaf(0.5f, tanha(0.5f * zi), 0.5f);
                float fg  = fmaf(0.5f, tanha(0.5f * zf), 0.5f);
                float gg2 = tanha(zg);
                float og  = fmaf(0.5f, tanha(0.5f * zz), 0.5f);
                float c = fg * c_[oi] + ig * gg2;
                c_[oi] = c;
                float hv = og * tanha(c);
                h_[oi] = hv;
                hsn[(pr0 + p) * XSTRIDE + j] = hv;
                if (rowok[oi]) {
                    float* op = &out[((size_t)(nbase + pr0 + p) * LL + te) * 128 + dir * 64 + j];
                    asm volatile("st.global.cs.f32 [%0], %1;" :: "l"(op), "f"(hv) : "memory");
                }
            }
        }
        asm volatile("bar.sync %0, %1;" :: "r"(barid), "r"(128) : "memory");
        buf ^= 1;
    }
}

extern "C" void kernel_launch(void* const* d_in, const int* in_sizes, int n_in,
                              void* d_out, int out_size) {
    const int*   ids   = (const int*)  d_in[0];
    const float* embed = (const float*)d_in[1];
    const float* Wk_f  = (const float*)d_in[2];
    const float* Wr_f  = (const float*)d_in[3];
    const float* b_f   = (const float*)d_in[4];
    const float* Wk_b  = (const float*)d_in[5];
    const float* Wr_b  = (const float*)d_in[6];
    const float* b_b   = (const float*)d_in[7];
    float* out = (float*)d_out;

    static bool attr_set = false;
    if (!attr_set) {
        cudaFuncSetAttribute(tab_kernel,
                             cudaFuncAttributeMaxDynamicSharedMemorySize,
                             K1_SMEM_FLOATS * (int)sizeof(float));
        cudaFuncSetAttribute(rec_kernel,
                             cudaFuncAttributeMaxDynamicSharedMemorySize,
                             K2_SMEM_FLOATS * (int)sizeof(float));
        attr_set = true;
    }

    dim3 grid1((VCAP + K1_ROWS_CTA - 1) / K1_ROWS_CTA, 2);   // 47 x 2
    tab_kernel<<<grid1, K1_NTHR, K1_SMEM_FLOATS * sizeof(float)>>>(
        embed, Wk_f, b_f, Wk_b, b_b);

    dim3 grid2(NCTA_X, 2);                                    // 74 x 2 = 148 CTAs
    rec_kernel<<<grid2, NTHR2, K2_SMEM_FLOATS * sizeof(float)>>>(
        ids, Wr_f, Wr_b, out);
}

// round 16
// speedup vs baseline: 2.1637x; 2.1637x over previous
#include <cuda_runtime.h>
#include <cuda_fp16.h>
#include <cstdint>

#define LL    256   // sequence length
#define EE    64    // embed dim
#define GG    256   // 4H
#define NSEQ  2048  // B*S
#define VV    6000  // vocab
#define VCAP  6016  // padded vocab rows in table

typedef unsigned long long u64;

// 12.3 MB scratch: T[dir][v][j*4+g] = embed[v] @ Wk_dir + b_dir  (L2-resident)
__device__ float g_tab[(size_t)2 * VCAP * GG];

__device__ __forceinline__ void fma2(u64 &d, u64 a, u64 b) {
    asm("fma.rn.f32x2 %0, %1, %2, %0;" : "+l"(d) : "l"(a), "l"(b));
}
__device__ __forceinline__ u64 pack2(float lo, float hi) {
    u64 r; asm("mov.b64 %0, {%1, %2};" : "=l"(r) : "f"(lo), "f"(hi)); return r;
}
__device__ __forceinline__ float hsum2(u64 v) {
    float lo, hi; asm("mov.b64 {%0, %1}, %2;" : "=f"(lo), "=f"(hi) : "l"(v));
    return lo + hi;
}
__device__ __forceinline__ float tanha(float x) {
    float y; asm("tanh.approx.f32 %0, %1;" : "=f"(y) : "f"(x)); return y;
}
__device__ __forceinline__ uint32_t s2u(const void* p) {
    uint32_t a;
    asm("{ .reg .u64 t; cvta.to.shared.u64 t, %1; cvt.u32.u64 %0, t; }"
        : "=r"(a) : "l"(p));
    return a;
}

#define XSTRIDE 68

// fp32 weight SMEM layout (K-paired for f32x2), two arrays (tab_kernel only)
template<int NT>
__device__ __forceinline__ void load_weights(float* w0, float* w1,
                                             const float* W, int tid) {
    for (int idx = tid; idx < 8192; idx += NT) {
        int e2  = idx >> 8;
        int rem = idx & 255;
        int jj  = rem >> 2;
        int g   = (rem >> 1) & 1;
        int s   = rem & 1;
        int e   = 2 * e2 + s;
        w0[idx] = W[e * GG + g * 64 + jj];
        w1[idx] = W[e * GG + (g + 2) * 64 + jj];
    }
}

// ============================================================================
// Kernel 1 (unchanged): vocab table T[dir][v] = embed[v] @ Wk_dir + b_dir
// ============================================================================
#define K1_NTHR 256
#define K1_TILES 8
#define K1_ROWS_CTA 128
#define K1_XS_G (2 * 4 * XSTRIDE)
#define K1_SMEM_FLOATS (16384 + 4 * K1_XS_G)

__global__ void __launch_bounds__(K1_NTHR, 1)
tab_kernel(const float* __restrict__ embed,
           const float* __restrict__ Wk_f, const float* __restrict__ b_f,
           const float* __restrict__ Wk_b, const float* __restrict__ b_b)
{
    extern __shared__ float smem[];
    float* wk0 = smem;
    float* wk1 = smem + 8192;

    const int tid = threadIdx.x;
    const int dir = blockIdx.y;
    const float* Wk = dir ? Wk_b : Wk_f;
    const float* bb = dir ? b_b  : b_f;

    load_weights<K1_NTHR>(wk0, wk1, Wk, tid);

    const int j     = tid & 63;
    const int q     = tid >> 6;
    const int barid = q + 1;
    float* xsg = smem + 16384 + q * K1_XS_G;

    const int grow = j >> 4;
    const int ge   = (j & 15) * 4;

    const float bi = bb[j], bf = bb[64 + j], bg = bb[128 + j], bo = bb[192 + j];

    const int v_base = blockIdx.x * K1_ROWS_CTA + q * (K1_TILES * 4);
    float* tb = g_tab + (size_t)dir * VCAP * GG;

    __syncthreads();

    float4 xv;
    {
        int v = v_base + grow; if (v >= VV) v = VV - 1;
        xv = *(const float4*)(embed + (size_t)v * EE + ge);
    }

    int buf = 0;
    for (int tile = 0; tile < K1_TILES; ++tile) {
        float* xs = xsg + buf * (4 * XSTRIDE);
        *(float4*)&xs[grow * XSTRIDE + ge] = xv;
        asm volatile("bar.sync %0, %1;" :: "r"(barid), "r"(64) : "memory");

        if (tile + 1 < K1_TILES) {
            int v = v_base + (tile + 1) * 4 + grow; if (v >= VV) v = VV - 1;
            xv = *(const float4*)(embed + (size_t)v * EE + ge);
        }

        u64 a0[4], a1[4], a2[4], a3[4];
#pragma unroll
        for (int p = 0; p < 4; ++p) {
            a0[p] = pack2(bi, 0.f);
            a1[p] = pack2(bf, 0.f);
            a2[p] = pack2(bg, 0.f);
            a3[p] = pack2(bo, 0.f);
        }

#pragma unroll 2
        for (int e4 = 0; e4 < 16; ++e4) {
            const ulonglong2 wA0 = *(const ulonglong2*)(wk0 + (2 * e4) * 256 + j * 4);
            const ulonglong2 wB0 = *(const ulonglong2*)(wk1 + (2 * e4) * 256 + j * 4);
            const ulonglong2 wA1 = *(const ulonglong2*)(wk0 + (2 * e4 + 1) * 256 + j * 4);
            const ulonglong2 wB1 = *(const ulonglong2*)(wk1 + (2 * e4 + 1) * 256 + j * 4);
#pragma unroll
            for (int p = 0; p < 4; ++p) {
                ulonglong2 x4 = *(const ulonglong2*)(xs + p * XSTRIDE + e4 * 4);
                fma2(a0[p], x4.x, wA0.x);
                fma2(a1[p], x4.x, wA0.y);
                fma2(a2[p], x4.x, wB0.x);
                fma2(a3[p], x4.x, wB0.y);
                fma2(a0[p], x4.y, wA1.x);
                fma2(a1[p], x4.y, wA1.y);
                fma2(a2[p], x4.y, wB1.x);
                fma2(a3[p], x4.y, wB1.y);
            }
        }

#pragma unroll
        for (int p = 0; p < 4; ++p) {
            int v = v_base + tile * 4 + p;
            if (v < VV) {
                float4 r;
                r.x = hsum2(a0[p]);
                r.y = hsum2(a1[p]);
                r.z = hsum2(a2[p]);
                r.w = hsum2(a3[p]);
                *(float4*)&tb[(size_t)v * GG + j * 4] = r;
            }
        }
        buf ^= 1;
    }
}

// ============================================================================
// Kernel 2: tensor-core recurrence. Per CTA-step: z[32x256] = h[32x64] @ Wr
// via mma.sync.m16n8k16 f16 (split-precision W = Whi + Wlo, both f16, frags
// register-resident; only h is f16-quantized). 256 thr = 8 warps, warp w owns
// N cols [32w,32w+32). h in SMEM as f16 (ldmatrix A), z exchanged via padded
// SMEM, epilogue thread owns (row=tid>>3, j=tid&7 + 8k). grid 64 x 2.
// ============================================================================
#define NTHR2 256
#define ROWS2 32
#define ZSTR  260                      // z row stride (floats)
#define HSTR  72                       // hs row stride (halves)
#define Z_FLOATS  (ROWS2 * ZSTR)       // 8320
#define HS_FLOATS ((ROWS2 * HSTR) / 2) // 1152
#define K2_SMEM_FLOATS (Z_FLOATS + HS_FLOATS + ROWS2 * LL)

__global__ void __launch_bounds__(NTHR2, 1)
rec_kernel(const int* __restrict__ ids,
           const float* __restrict__ Wr_f,
           const float* __restrict__ Wr_b,
           float* __restrict__ out)
{
    extern __shared__ float smem[];
    float*  zbuf = smem;                                  // [32][260]
    __half* hsb  = (__half*)(smem + Z_FLOATS);            // [32][72]
    int*    idss = (int*)(smem + Z_FLOATS + HS_FLOATS);   // [32][256]

    const int tid = threadIdx.x;
    const int ln  = tid & 31;
    const int w   = tid >> 5;          // warp 0..7, owns cols [32w, 32w+32)
    const int dir = blockIdx.y;
    const int nbase = blockIdx.x * ROWS2;
    const float* Wr = dir ? Wr_b : Wr_f;

    // stage ids; zero h (t=0 state)
    for (int idx = tid; idx < ROWS2 * LL; idx += NTHR2)
        idss[idx] = ids[(size_t)(nbase + idx / LL) * LL + (idx % LL)];
    for (int idx = tid; idx < HS_FLOATS; idx += NTHR2)
        ((uint32_t*)hsb)[idx] = 0;

    // ---- resident B fragments: split-precision f16 weights ----
    // z col c (gate-interleaved: c = j*4+g) <- Wr original col g*64+j.
    uint32_t Bhi[4][4][2], Blo[4][4][2];
    {
        const int kb = 2 * (ln & 3);
        const int cb = w * 32 + (ln >> 2);
#pragma unroll
        for (int kt = 0; kt < 4; ++kt)
#pragma unroll
            for (int nt = 0; nt < 4; ++nt) {
                int c  = cb + nt * 8;
                int oc = (c & 3) * 64 + (c >> 2);   // original Wr column
#pragma unroll
                for (int hh = 0; hh < 2; ++hh) {
                    int k0 = kt * 16 + kb + hh * 8;
                    float f0 = Wr[k0 * GG + oc];
                    float f1 = Wr[(k0 + 1) * GG + oc];
                    __half h0 = __float2half_rn(f0);
                    __half h1 = __float2half_rn(f1);
                    __half l0 = __float2half_rn(f0 - __half2float(h0));
                    __half l1 = __float2half_rn(f1 - __half2float(h1));
                    Bhi[kt][nt][hh] = ((uint32_t)__half_as_ushort(h1) << 16) |
                                      (uint32_t)__half_as_ushort(h0);
                    Blo[kt][nt][hh] = ((uint32_t)__half_as_ushort(l1) << 16) |
                                      (uint32_t)__half_as_ushort(l0);
                }
            }
    }

    // epilogue ownership: 8 cells (erow, ej0 + 8k)
    const int erow = tid >> 3;
    const int ej0  = tid & 7;

    float c_[8], h_[8];
    float4 pv[8];
#pragma unroll
    for (int k = 0; k < 8; ++k) { c_[k] = 0.f; h_[k] = 0.f; }

    const float* tb = g_tab + (size_t)dir * VCAP * GG;

    // ldmatrix per-lane address base (A tile (mt,kt): rows mt*16+(ln&15),
    // col halves kt*16 + (ln>>4)*8)
    const uint32_t hsA = s2u(hsb) + (ln & 15) * (HSTR * 2) + (ln >> 4) * 16;

    __syncthreads();   // ids + hs-zero visible

    // prefetch table rows for step 0
    {
        const int te0 = dir ? (LL - 1) : 0;
        int id = idss[erow * LL + te0];
#pragma unroll
        for (int k = 0; k < 8; ++k)
            pv[k] = *(const float4*)&tb[(size_t)id * GG + 4 * (ej0 + 8 * k)];
    }

    for (int t = 0; t < LL; ++t) {
        const int te = dir ? (LL - 1 - t) : t;

        __syncthreads();   // barA: hs ready, z free

        // A fragments via ldmatrix
        uint32_t A[2][4][4];
#pragma unroll
        for (int mt = 0; mt < 2; ++mt)
#pragma unroll
            for (int kt = 0; kt < 4; ++kt) {
                uint32_t a = hsA + mt * (16 * HSTR * 2) + kt * 32;
                asm volatile(
                    "ldmatrix.sync.aligned.m8n8.x4.shared.b16 {%0,%1,%2,%3}, [%4];"
                    : "=r"(A[mt][kt][0]), "=r"(A[mt][kt][1]),
                      "=r"(A[mt][kt][2]), "=r"(A[mt][kt][3])
                    : "r"(a));
            }

        // mma (hi + lo) and z STS per tile
#pragma unroll
        for (int mt = 0; mt < 2; ++mt)
#pragma unroll
            for (int nt = 0; nt < 4; ++nt) {
                float c0 = 0.f, c1 = 0.f, c2 = 0.f, c3 = 0.f;
#pragma unroll
                for (int kt = 0; kt < 4; ++kt) {
                    asm volatile(
                        "mma.sync.aligned.m16n8k16.row.col.f32.f16.f16.f32 "
                        "{%0,%1,%2,%3}, {%4,%5,%6,%7}, {%8,%9}, {%0,%1,%2,%3};"
                        : "+f"(c0), "+f"(c1), "+f"(c2), "+f"(c3)
                        : "r"(A[mt][kt][0]), "r"(A[mt][kt][1]),
                          "r"(A[mt][kt][2]), "r"(A[mt][kt][3]),
                          "r"(Bhi[kt][nt][0]), "r"(Bhi[kt][nt][1]));
                    asm volatile(
                        "mma.sync.aligned.m16n8k16.row.col.f32.f16.f16.f32 "
                        "{%0,%1,%2,%3}, {%4,%5,%6,%7}, {%8,%9}, {%0,%1,%2,%3};"
                        : "+f"(c0), "+f"(c1), "+f"(c2), "+f"(c3)
                        : "r"(A[mt][kt][0]), "r"(A[mt][kt][1]),
                          "r"(A[mt][kt][2]), "r"(A[mt][kt][3]),
                          "r"(Blo[kt][nt][0]), "r"(Blo[kt][nt][1]));
                }
                int zr = mt * 16 + (ln >> 2);
                int zc = w * 32 + nt * 8 + 2 * (ln & 3);
                *(float2*)&zbuf[zr * ZSTR + zc]       = make_float2(c0, c1);
                *(float2*)&zbuf[(zr + 8) * ZSTR + zc] = make_float2(c2, c3);
            }

        __syncthreads();   // barB: z ready, hs consumable for rewrite

        // epilogue: z + pre -> gates -> c,h ; write h (f16) + out (f32)
#pragma unroll
        for (int k = 0; k < 8; ++k) {
            int j = ej0 + 8 * k;
            float4 z4 = *(const float4*)&zbuf[erow * ZSTR + 4 * j];
            float zi = z4.x + pv[k].x;
            float zf = z4.y + pv[k].y;
            float zg = z4.z + pv[k].z;
            float zo = z4.w + pv[k].w;
            float ig  = fmaf(0.5f, tanha(0.5f * zi), 0.5f);
            float fg  = fmaf(0.5f, tanha(0.5f * zf), 0.5f);
            float gg2 = tanha(zg);
            float og  = fmaf(0.5f, tanha(0.5f * zo), 0.5f);
            float c = fg * c_[k] + ig * gg2;
            c_[k] = c;
            float hv = og * tanha(c);
            h_[k] = hv;
            hsb[erow * HSTR + j] = __float2half_rn(hv);
            float* op = &out[((size_t)(nbase + erow) * LL + te) * 128 + dir * 64 + j];
            asm volatile("st.global.cs.f32 [%0], %1;" :: "l"(op), "f"(hv) : "memory");
        }

        // prefetch table rows for t+1 (lands under next step's mma)
        {
            const int tn = (t + 1 < LL) ? (dir ? (LL - 2 - t) : (t + 1)) : te;
            int id = idss[erow * LL + tn];
#pragma unroll
            for (int k = 0; k < 8; ++k)
                pv[k] = *(const float4*)&tb[(size_t)id * GG + 4 * (ej0 + 8 * k)];
        }
    }
}

extern "C" void kernel_launch(void* const* d_in, const int* in_sizes, int n_in,
                              void* d_out, int out_size) {
    const int*   ids   = (const int*)  d_in[0];
    const float* embed = (const float*)d_in[1];
    const float* Wk_f  = (const float*)d_in[2];
    const float* Wr_f  = (const float*)d_in[3];
    const float* b_f   = (const float*)d_in[4];
    const float* Wk_b  = (const float*)d_in[5];
    const float* Wr_b  = (const float*)d_in[6];
    const float* b_b   = (const float*)d_in[7];
    float* out = (float*)d_out;

    static bool attr_set = false;
    if (!attr_set) {
        cudaFuncSetAttribute(tab_kernel,
                             cudaFuncAttributeMaxDynamicSharedMemorySize,
                             K1_SMEM_FLOATS * (int)sizeof(float));
        cudaFuncSetAttribute(rec_kernel,
                             cudaFuncAttributeMaxDynamicSharedMemorySize,
                             K2_SMEM_FLOATS * (int)sizeof(float));
        attr_set = true;
    }

    dim3 grid1((VCAP + K1_ROWS_CTA - 1) / K1_ROWS_CTA, 2);   // 47 x 2
    tab_kernel<<<grid1, K1_NTHR, K1_SMEM_FLOATS * sizeof(float)>>>(
        embed, Wk_f, b_f, Wk_b, b_b);

    dim3 grid2(NSEQ / ROWS2, 2);                              // 64 x 2
    rec_kernel<<<grid2, NTHR2, K2_SMEM_FLOATS * sizeof(float)>>>(
        ids, Wr_f, Wr_b, out);
}